// round 3
// baseline (speedup 1.0000x reference)
#include <cuda_runtime.h>

#define TLEN  512
#define BATCH 1024
#define HID   128
#define G4    512
#define NCLS  6
#define BT    16
#define KPAD0 144    // 16 (padded x, C=9) + 128 (h)
#define KPAD1 384    // 256 (x = layer0 out) + 128 (h)

// ---------------------------------------------------------------------------
// Scratch (device globals; no allocations allowed)
// ---------------------------------------------------------------------------
__device__ __align__(16) float g_xT[(size_t)TLEN * BATCH * 16];       // 32 MB
__device__ __align__(16) float g_out0[(size_t)TLEN * BATCH * 256];    // 512 MB
__device__ __align__(16) float g_final[(size_t)BATCH * 256];          // 1 MB
__device__ __align__(16) float g_wp0[2 * KPAD0 * G4];                 // packed L0 weights
__device__ __align__(16) float g_wp1[2 * KPAD1 * G4];                 // packed L1 weights
__device__ float g_bias[4 * G4];                                      // b_ih+b_hh per (layer,dir)

// ---------------------------------------------------------------------------
// Helpers
// ---------------------------------------------------------------------------
__device__ __forceinline__ unsigned long long ffma2(unsigned long long a,
                                                    unsigned long long b,
                                                    unsigned long long c) {
    unsigned long long d;
    asm("fma.rn.f32x2 %0, %1, %2, %3;" : "=l"(d) : "l"(a), "l"(b), "l"(c));
    return d;
}
__device__ __forceinline__ float upsum(unsigned long long a) {
    float lo, hi;
    asm("mov.b64 {%0, %1}, %2;" : "=f"(lo), "=f"(hi) : "l"(a));
    return lo + hi;
}
__device__ __forceinline__ float sigm(float x) {
    return __fdividef(1.f, 1.f + __expf(-x));
}
__device__ __forceinline__ float tanhx(float x) {
    return __fdividef(2.f, 1.f + __expf(-2.f * x)) - 1.f;   // no NaN at saturation
}

// ---------------------------------------------------------------------------
// Prep: transpose x [B,9,T] -> g_xT [T,B,16] (cols 9..15 zero)
// ---------------------------------------------------------------------------
__global__ void k_transpose(const float* __restrict__ x) {
    size_t o = (size_t)blockIdx.x * blockDim.x + threadIdx.x;
    if (o >= (size_t)TLEN * BATCH * 16) return;
    int c = (int)(o & 15);
    size_t tb = o >> 4;
    int b = (int)(tb % BATCH);
    int t = (int)(tb / BATCH);
    g_xT[o] = (c < 9) ? x[((size_t)b * 9 + c) * TLEN + t] : 0.f;
}

// ---------------------------------------------------------------------------
// Prep: pack weights into k-quad-interleaved layout wp[kk][g][4],
// z layout = [x (xoff cols, padded) | h (128)].  which: 0=l0f 1=l0r 2=l1f 3=l1r
// ---------------------------------------------------------------------------
__global__ void k_pack(const float* __restrict__ wih, const float* __restrict__ whh,
                       const float* __restrict__ bih, const float* __restrict__ bhh,
                       int which) {
    const int kpad   = (which < 2) ? KPAD0 : KPAD1;
    const int in_dim = (which < 2) ? 9 : 256;
    const int xoff   = (which < 2) ? 16 : 256;
    float* wp = (which < 2) ? (g_wp0 + which * KPAD0 * G4)
                            : (g_wp1 + (which - 2) * KPAD1 * G4);
    int o = blockIdx.x * blockDim.x + threadIdx.x;
    if (o < G4) g_bias[which * G4 + o] = bih[o] + bhh[o];
    if (o >= kpad * G4) return;
    int kk  = o / (G4 * 4);
    int rem = o % (G4 * 4);
    int g = rem / 4;
    int j = rem % 4;
    int k = kk * 4 + j;
    float v = 0.f;
    if (k < in_dim)                       v = wih[g * in_dim + k];
    else if (k >= xoff && k < xoff + HID) v = whh[g * HID + (k - xoff)];
    wp[o] = v;
}

// ---------------------------------------------------------------------------
// BiLSTM direction-layer scan. One block = 16 batch rows, whole time scan.
// blockIdx.x: batch tile (64), blockIdx.y: direction (0 fwd, 1 rev).
// 256 threads; thread tid computes gates (tid, tid+256) for all 16 rows.
// ---------------------------------------------------------------------------
template <bool L0>
__global__ void __launch_bounds__(256, 1) k_lstm() {
    constexpr int KPAD = L0 ? KPAD0 : KPAD1;
    constexpr int XW   = L0 ? 16 : 256;
    constexpr int KQ   = KPAD / 4;

    extern __shared__ float smem[];
    float* zsm = smem;                    // [BT][KPAD]  z = [x | h]
    float* gsm = smem + BT * KPAD;        // [BT][G4]    gates
    float* csm = gsm + BT * G4;           // [BT][HID]   cell state

    const int tid = threadIdx.x;
    const int dir = blockIdx.y;
    const int b0  = blockIdx.x * BT;
    const int g0  = tid, g1 = tid + 256;

    const float* wpraw = L0 ? (g_wp0 + dir * KPAD0 * G4) : (g_wp1 + dir * KPAD1 * G4);
    const ulonglong2* __restrict__ wp = (const ulonglong2*)wpraw;
    const float* biasp = g_bias + (L0 ? 0 : 2 * G4) + dir * G4;
    const float bs0 = biasp[g0], bs1 = biasp[g1];
    const float* __restrict__ xin = L0 ? g_xT : g_out0;

    for (int i = tid; i < BT * KPAD; i += 256) zsm[i] = 0.f;   // h starts 0
    for (int i = tid; i < BT * HID;  i += 256) csm[i] = 0.f;   // c starts 0
    __syncthreads();

    for (int t = 0; t < TLEN; ++t) {
        const int tg = dir ? (TLEN - 1 - t) : t;

        // ---- load x_t slice into z x-section (coalesced float4) ----
        const float4* src = (const float4*)(xin + ((size_t)tg * BATCH + b0) * XW);
        for (int i = tid; i < BT * (XW / 4); i += 256) {
            int b = i / (XW / 4), c = i % (XW / 4);
            *(float4*)&zsm[b * KPAD + c * 4] = src[b * (XW / 4) + c];
        }
        __syncthreads();   // x ready + h from prev step ready

        // ---- gates = z @ Wcat^T, packed f32x2 over k ----
        unsigned long long a0[BT], a1[BT];
#pragma unroll
        for (int b = 0; b < BT; b++) { a0[b] = 0ull; a1[b] = 0ull; }

        ulonglong2 w0n = wp[g0];
        ulonglong2 w1n = wp[g1];
        for (int kk = 0; kk < KQ; kk++) {
            ulonglong2 w0 = w0n, w1 = w1n;
            if (kk + 1 < KQ) {             // 1-quad-ahead weight prefetch (L2)
                w0n = wp[(kk + 1) * G4 + g0];
                w1n = wp[(kk + 1) * G4 + g1];
            }
            const ulonglong2* zq = (const ulonglong2*)(zsm + kk * 4);
#pragma unroll
            for (int b = 0; b < BT; b++) {
                ulonglong2 zb = zq[b * (KPAD / 4)];   // warp-broadcast LDS.128
                a0[b] = ffma2(zb.x, w0.x, a0[b]);
                a0[b] = ffma2(zb.y, w0.y, a0[b]);
                a1[b] = ffma2(zb.x, w1.x, a1[b]);
                a1[b] = ffma2(zb.y, w1.y, a1[b]);
            }
        }

#pragma unroll
        for (int b = 0; b < BT; b++) {
            gsm[b * G4 + g0] = upsum(a0[b]) + bs0;
            gsm[b * G4 + g1] = upsum(a1[b]) + bs1;
        }
        __syncthreads();   // gates visible to cell-update owners

        // ---- elementwise cell update: thread -> (b, 8 consecutive j) ----
        {
            const int b  = tid >> 4;
            const int j0 = (tid & 15) * 8;
            const float* gb = gsm + b * G4;
            float* cb = csm + b * HID;
            float hv[8];
#pragma unroll
            for (int u = 0; u < 8; u++) {
                int j = j0 + u;
                float gi = sigm(gb[j]);
                float gf = sigm(gb[HID + j]);
                float gg = tanhx(gb[2 * HID + j]);
                float go = sigm(gb[3 * HID + j]);
                float c  = gf * cb[j] + gi * gg;
                cb[j] = c;
                hv[u] = go * tanhx(c);
            }
            float* zh = zsm + b * KPAD + XW + j0;
            *(float4*)zh       = make_float4(hv[0], hv[1], hv[2], hv[3]);
            *(float4*)(zh + 4) = make_float4(hv[4], hv[5], hv[6], hv[7]);
            if (L0) {
                float* dst = g_out0 + ((size_t)tg * BATCH + b0 + b) * 256 + dir * HID + j0;
                *(float4*)dst       = make_float4(hv[0], hv[1], hv[2], hv[3]);
                *(float4*)(dst + 4) = make_float4(hv[4], hv[5], hv[6], hv[7]);
            }
        }
        // no extra sync: next x-load touches a disjoint smem region; the
        // loop-top __syncthreads orders h-writes before the next gate GEMM.
    }

    if (!L0) {
        __syncthreads();
        for (int i = tid; i < BT * HID; i += 256) {
            int b = i >> 7, j = i & 127;
            g_final[(size_t)(b0 + b) * 256 + dir * HID + j] = zsm[b * KPAD + XW + j];
        }
    }
}

// ---------------------------------------------------------------------------
// Classifier: out[b] = final[b] @ w_cls^T + b_cls, one warp per batch row
// ---------------------------------------------------------------------------
__global__ void k_cls(const float* __restrict__ wc, const float* __restrict__ bc,
                      float* __restrict__ out) {
    int gw   = (blockIdx.x * blockDim.x + threadIdx.x) >> 5;
    int lane = threadIdx.x & 31;
    if (gw >= BATCH) return;
    const float* f = g_final + (size_t)gw * 256;
    float v[8];
#pragma unroll
    for (int i = 0; i < 8; i++) v[i] = f[lane + 32 * i];
#pragma unroll
    for (int nc = 0; nc < NCLS; nc++) {
        float s = 0.f;
#pragma unroll
        for (int i = 0; i < 8; i++) s += v[i] * wc[nc * 256 + lane + 32 * i];
#pragma unroll
        for (int off = 16; off; off >>= 1) s += __shfl_down_sync(0xffffffffu, s, off);
        if (lane == 0) out[gw * NCLS + nc] = s + bc[nc];
    }
}

// ---------------------------------------------------------------------------
extern "C" void kernel_launch(void* const* d_in, const int* in_sizes, int n_in,
                              void* d_out, int out_size) {
    (void)in_sizes; (void)n_in; (void)out_size;
    const float* x = (const float*)d_in[0];

    const int smem0 = (BT * KPAD0 + BT * G4 + BT * HID) * 4;   // ~50 KB
    const int smem1 = (BT * KPAD1 + BT * G4 + BT * HID) * 4;   // 64 KB
    (void)cudaFuncSetAttribute(k_lstm<true>,  cudaFuncAttributeMaxDynamicSharedMemorySize, smem1);
    (void)cudaFuncSetAttribute(k_lstm<false>, cudaFuncAttributeMaxDynamicSharedMemorySize, smem1);

    k_transpose<<<(TLEN * BATCH * 16 + 255) / 256, 256>>>(x);
    k_pack<<<(KPAD0 * G4 + 255) / 256, 256>>>((const float*)d_in[1],  (const float*)d_in[2],
                                              (const float*)d_in[3],  (const float*)d_in[4],  0);
    k_pack<<<(KPAD0 * G4 + 255) / 256, 256>>>((const float*)d_in[5],  (const float*)d_in[6],
                                              (const float*)d_in[7],  (const float*)d_in[8],  1);
    k_pack<<<(KPAD1 * G4 + 255) / 256, 256>>>((const float*)d_in[9],  (const float*)d_in[10],
                                              (const float*)d_in[11], (const float*)d_in[12], 2);
    k_pack<<<(KPAD1 * G4 + 255) / 256, 256>>>((const float*)d_in[13], (const float*)d_in[14],
                                              (const float*)d_in[15], (const float*)d_in[16], 3);

    k_lstm<true ><<<dim3(BATCH / BT, 2), 256, smem0>>>();
    k_lstm<false><<<dim3(BATCH / BT, 2), 256, smem1>>>();

    k_cls<<<BATCH / 8, 256>>>((const float*)d_in[17], (const float*)d_in[18], (float*)d_out);
}

// round 9
// speedup vs baseline: 1.2035x; 1.2035x over previous
#include <cuda_runtime.h>
#include <cuda_bf16.h>
#include <cstdint>

#define TLEN  512
#define BATCH 1024
#define HID   128
#define G4    512
#define NCLS  6
#define BT    16
#define KPAD0 144    // 16 (padded x, C=9) + 128 (h)
#define KPAD1 128    // h only (input projection precomputed)
#define SEGT  128    // timesteps per L1 segment
#define NSEG  (TLEN / SEGT)

// ---------------------------------------------------------------------------
// Scratch (device globals; total must stay well under 2 GB — host shadow .bss)
// ---------------------------------------------------------------------------
__device__ __align__(16) float g_xT[(size_t)TLEN * BATCH * 16];              // 32 MB
__device__ __align__(16) __nv_bfloat16 g_ah[(size_t)TLEN * BATCH * 256];     // 256 MB
__device__ __align__(16) __nv_bfloat16 g_al[(size_t)TLEN * BATCH * 256];     // 256 MB
__device__ __align__(16) float g_xg1f[(size_t)SEGT * BATCH * G4];            // 256 MB (fwd chunk)
__device__ __align__(16) float g_xg1r[(size_t)SEGT * BATCH * G4];            // 256 MB (rev chunk)
__device__ __align__(16) float g_hstate[2 * BATCH * HID];                    // 1 MB
__device__ __align__(16) float g_cstate[2 * BATCH * HID];                    // 1 MB
__device__ __align__(16) float g_final[(size_t)BATCH * 256];
__device__ __align__(16) float g_wp0[2 * KPAD0 * G4];
__device__ __align__(16) float g_wp1[2 * KPAD1 * G4];
__device__ __align__(16) __nv_bfloat16 g_wb1h[2 * 512 * 256];                // W_ih_l1 bf16 hi [dir][n][k]
__device__ __align__(16) __nv_bfloat16 g_wb1l[2 * 512 * 256];                // W_ih_l1 bf16 lo
__device__ float g_bias[4 * G4];

// Single dynamic-smem symbol (one type everywhere)
extern __shared__ char smem_raw[];

// ---------------------------------------------------------------------------
// Scalar helpers
// ---------------------------------------------------------------------------
__device__ __forceinline__ unsigned long long ffma2(unsigned long long a,
                                                    unsigned long long b,
                                                    unsigned long long c) {
    unsigned long long d;
    asm("fma.rn.f32x2 %0, %1, %2, %3;" : "=l"(d) : "l"(a), "l"(b), "l"(c));
    return d;
}
__device__ __forceinline__ float upsum(unsigned long long a) {
    float lo, hi;
    asm("mov.b64 {%0, %1}, %2;" : "=f"(lo), "=f"(hi) : "l"(a));
    return lo + hi;
}
__device__ __forceinline__ unsigned long long pack2(float lo, float hi) {
    unsigned long long r;
    asm("mov.b64 %0, {%1, %2};" : "=l"(r) : "f"(lo), "f"(hi));
    return r;
}
__device__ __forceinline__ float sigm(float x) {
    return __fdividef(1.f, 1.f + __expf(-x));
}
__device__ __forceinline__ float tanhx(float x) {
    return __fdividef(2.f, 1.f + __expf(-2.f * x)) - 1.f;
}

// mma.sync m16n8k16 bf16 -> fp32 accumulate (sm_80+, valid on family target)
__device__ __forceinline__ void mma16816(float* c,
                                         uint32_t a0, uint32_t a1, uint32_t a2, uint32_t a3,
                                         uint32_t b0, uint32_t b1) {
    asm volatile(
        "mma.sync.aligned.m16n8k16.row.col.f32.bf16.bf16.f32 "
        "{%0,%1,%2,%3}, {%4,%5,%6,%7}, {%8,%9}, {%0,%1,%2,%3};"
        : "+f"(c[0]), "+f"(c[1]), "+f"(c[2]), "+f"(c[3])
        : "r"(a0), "r"(a1), "r"(a2), "r"(a3), "r"(b0), "r"(b1));
}

// ---------------------------------------------------------------------------
// Prep: transpose x [B,9,T] -> g_xT [T,B,16] (cols 9..15 zero)
// ---------------------------------------------------------------------------
__global__ void k_transpose(const float* __restrict__ x) {
    size_t o = (size_t)blockIdx.x * blockDim.x + threadIdx.x;
    if (o >= (size_t)TLEN * BATCH * 16) return;
    int c = (int)(o & 15);
    size_t tb = o >> 4;
    int b = (int)(tb % BATCH);
    int t = (int)(tb / BATCH);
    g_xT[o] = (c < 9) ? x[((size_t)b * 9 + c) * TLEN + t] : 0.f;
}

// ---------------------------------------------------------------------------
// Pack scan weights, quad-interleaved wp[kk][g][4]; bias sums.
// which: 0=l0f 1=l0r (K=144), 2=l1f 3=l1r (K=128, h only)
// ---------------------------------------------------------------------------
struct WPtrs { const float* p[16]; };

__global__ void k_pack_whh(WPtrs W) {
    const int which = blockIdx.y;
    const float* wih = W.p[which * 4 + 0];
    const float* whh = W.p[which * 4 + 1];
    const float* bih = W.p[which * 4 + 2];
    const float* bhh = W.p[which * 4 + 3];
    const int kpad = (which < 2) ? KPAD0 : KPAD1;
    int o = blockIdx.x * blockDim.x + threadIdx.x;
    if (o < G4) g_bias[which * G4 + o] = bih[o] + bhh[o];
    if (o >= kpad * G4) return;
    int kk = o / (G4 * 4);
    int rem = o % (G4 * 4);
    int g = rem / 4, j = rem % 4;
    int k = kk * 4 + j;
    float v = 0.f;
    if (which < 2) {
        if (k < 9)                      v = wih[g * 9 + k];
        else if (k >= 16 && k < 144)    v = whh[g * HID + (k - 16)];
        g_wp0[which * KPAD0 * G4 + o] = v;
    } else {
        v = whh[g * HID + k];
        g_wp1[(which - 2) * KPAD1 * G4 + o] = v;
    }
}

// ---------------------------------------------------------------------------
// Pack W_ih_l1 fp32 -> bf16 hi/lo, plain [dir][512 n][256 k] row-major
// ---------------------------------------------------------------------------
__global__ void k_pack_wb1(const float* __restrict__ wf, const float* __restrict__ wr) {
    int o = blockIdx.x * blockDim.x + threadIdx.x;
    if (o >= 2 * G4 * 256) return;
    int dir = o / (G4 * 256);
    int rem = o % (G4 * 256);
    const float* w = dir ? wr : wf;
    float v = w[rem];
    __nv_bfloat16 h = __float2bfloat16(v);
    __nv_bfloat16 l = __float2bfloat16(v - __bfloat162float(h));
    g_wb1h[o] = h;
    g_wb1l[o] = l;
}

// ---------------------------------------------------------------------------
// xg1 chunk: for segment seg, per dir, compute xg = out0 @ W_ih_l1^T + bias
// over SEGT timesteps. Grid (512, 8): y = dir*4 + ntile. Block 256 thr =
// 8 warps (4m x 2n), tile 256m x 128n x K256, atom m16n8k16, bf16 3-split.
// ---------------------------------------------------------------------------
#define BSTR 264   // B smem row stride (bf16)
#define ASTR 40    // A smem row stride (bf16)

__global__ void __launch_bounds__(256, 1) k_xg1(int seg) {
    __nv_bfloat16* sBh = (__nv_bfloat16*)smem_raw;
    __nv_bfloat16* sBl = sBh + 128 * BSTR;
    __nv_bfloat16* sAh = sBl + 128 * BSTR;
    __nv_bfloat16* sAl = sAh + 256 * ASTR;

    const int tid  = threadIdx.x;
    const int wid  = tid >> 5, lane = tid & 31;
    const int g    = lane >> 2, tig = lane & 3;
    const int wm   = (wid & 3) * 64;
    const int wn   = (wid >> 2) * 64;
    const int dir  = blockIdx.y >> 2;
    const int n0   = (blockIdx.y & 3) * 128;
    const int t0   = dir ? (TLEN - (seg + 1) * SEGT) : (seg * SEGT);
    const size_t mg0 = (size_t)t0 * BATCH + (size_t)blockIdx.x * 256;   // global A row
    const size_t ml0 = (size_t)blockIdx.x * 256;                         // local out row

    // ---- B tile (128 n-rows x 256 k) hi+lo ----
    {
        const uint4* gh = (const uint4*)(g_wb1h + ((size_t)dir * 512 + n0) * 256);
        const uint4* gl = (const uint4*)(g_wb1l + ((size_t)dir * 512 + n0) * 256);
        for (int i = tid; i < 128 * 32; i += 256) {
            int r = i >> 5, c = i & 31;
            *(uint4*)(sBh + r * BSTR + c * 8) = gh[r * 32 + c];
            *(uint4*)(sBl + r * BSTR + c * 8) = gl[r * 32 + c];
        }
    }

    float acc[4][8][4];
#pragma unroll
    for (int mf = 0; mf < 4; mf++)
#pragma unroll
        for (int j = 0; j < 8; j++)
#pragma unroll
            for (int q = 0; q < 4; q++) acc[mf][j][q] = 0.f;

    for (int kc = 0; kc < 8; kc++) {
        __syncthreads();   // B ready (iter 0) / previous A reads done
        for (int i = tid; i < 256 * 4; i += 256) {
            int r = i >> 2, c = i & 3;
            *(uint4*)(sAh + r * ASTR + c * 8) =
                *(const uint4*)(g_ah + (mg0 + r) * 256 + kc * 32 + c * 8);
            *(uint4*)(sAl + r * ASTR + c * 8) =
                *(const uint4*)(g_al + (mg0 + r) * 256 + kc * 32 + c * 8);
        }
        __syncthreads();

#pragma unroll
        for (int s = 0; s < 2; s++) {
            uint32_t bh[8][2], bl[8][2];
            const int kkb = kc * 32 + s * 16 + 2 * tig;
#pragma unroll
            for (int j = 0; j < 8; j++) {
                const int n = wn + j * 8 + g;
                bh[j][0] = *(const uint32_t*)(sBh + n * BSTR + kkb);
                bh[j][1] = *(const uint32_t*)(sBh + n * BSTR + kkb + 8);
                bl[j][0] = *(const uint32_t*)(sBl + n * BSTR + kkb);
                bl[j][1] = *(const uint32_t*)(sBl + n * BSTR + kkb + 8);
            }
            const int ka = s * 16 + 2 * tig;
#pragma unroll
            for (int mf = 0; mf < 4; mf++) {
                const int mr = wm + mf * 16 + g;
                uint32_t ah0 = *(const uint32_t*)(sAh + mr * ASTR + ka);
                uint32_t ah1 = *(const uint32_t*)(sAh + (mr + 8) * ASTR + ka);
                uint32_t ah2 = *(const uint32_t*)(sAh + mr * ASTR + ka + 8);
                uint32_t ah3 = *(const uint32_t*)(sAh + (mr + 8) * ASTR + ka + 8);
                uint32_t al0 = *(const uint32_t*)(sAl + mr * ASTR + ka);
                uint32_t al1 = *(const uint32_t*)(sAl + (mr + 8) * ASTR + ka);
                uint32_t al2 = *(const uint32_t*)(sAl + mr * ASTR + ka + 8);
                uint32_t al3 = *(const uint32_t*)(sAl + (mr + 8) * ASTR + ka + 8);
#pragma unroll
                for (int j = 0; j < 8; j++) {
                    mma16816(acc[mf][j], ah0, ah1, ah2, ah3, bh[j][0], bh[j][1]);
                    mma16816(acc[mf][j], ah0, ah1, ah2, ah3, bl[j][0], bl[j][1]);
                    mma16816(acc[mf][j], al0, al1, al2, al3, bh[j][0], bh[j][1]);
                }
            }
        }
    }

    // ---- epilogue: +bias, write fp32 xg chunk ----
    float* out = dir ? g_xg1r : g_xg1f;
    const float* bias = g_bias + (2 + dir) * G4 + n0;
#pragma unroll
    for (int mf = 0; mf < 4; mf++) {
#pragma unroll
        for (int j = 0; j < 8; j++) {
            const int col = wn + j * 8 + 2 * tig;
            const size_t row = ml0 + wm + mf * 16 + g;
            float2 bv = *(const float2*)(bias + col);
            float2 v0 = make_float2(acc[mf][j][0] + bv.x, acc[mf][j][1] + bv.y);
            float2 v1 = make_float2(acc[mf][j][2] + bv.x, acc[mf][j][3] + bv.y);
            *(float2*)(out + row * G4 + n0 + col)       = v0;
            *(float2*)(out + (row + 8) * G4 + n0 + col) = v1;
        }
    }
}

// ---------------------------------------------------------------------------
// BiLSTM direction-layer scan.
// L0: full T, K=144 (x fused), writes bf16 hi/lo out0.
// L1: one SEGT segment, K=128, xg-chunk init, h/c carried via g_*state.
// ---------------------------------------------------------------------------
template <bool L0>
__global__ void __launch_bounds__(256, 1) k_lstm(int seg) {
    constexpr int KPAD = L0 ? KPAD0 : KPAD1;
    constexpr int XW   = L0 ? 16 : 0;
    constexpr int KQ   = KPAD / 4;
    constexpr int NT   = L0 ? TLEN : SEGT;

    float* smem = (float*)smem_raw;
    float* zsm = smem;                    // [BT][KPAD]  z = [x | h]
    float* gsm = smem + BT * KPAD;        // [BT][G4]
    float* csm = gsm + BT * G4;           // [BT][HID]

    const int tid = threadIdx.x;
    const int dir = blockIdx.y;
    const int b0  = blockIdx.x * BT;
    const int g0  = tid, g1 = tid + 256;

    const float* wpraw = L0 ? (g_wp0 + dir * KPAD0 * G4) : (g_wp1 + dir * KPAD1 * G4);
    const ulonglong2* __restrict__ wp = (const ulonglong2*)wpraw;
    float bs0 = 0.f, bs1 = 0.f;
    if (L0) { bs0 = g_bias[dir * G4 + g0]; bs1 = g_bias[dir * G4 + g1]; }
    const float* __restrict__ xgb = L0 ? nullptr : (dir ? g_xg1r : g_xg1f);
    const int tbase = L0 ? 0 : (dir ? (TLEN - (seg + 1) * SEGT) : (seg * SEGT));

    if (L0 || seg == 0) {
        for (int i = tid; i < BT * KPAD; i += 256) zsm[i] = 0.f;
        for (int i = tid; i < BT * HID;  i += 256) csm[i] = 0.f;
    } else {
        for (int i = tid; i < BT * HID; i += 256) {
            int b = i >> 7, j = i & 127;
            zsm[b * KPAD + XW + j] = g_hstate[(dir * BATCH + b0 + b) * HID + j];
            csm[b * HID + j]       = g_cstate[(dir * BATCH + b0 + b) * HID + j];
        }
        if (XW > 0) {
            for (int i = tid; i < BT * XW; i += 256) {
                int b = i / XW, c = i % XW;
                zsm[b * KPAD + c] = 0.f;   // (unused branch; kept for symmetry)
            }
        }
    }
    __syncthreads();

    for (int t = 0; t < NT; ++t) {
        // global time index for this step
        const int tg = dir ? (TLEN - 1 - (L0 ? t : (seg * SEGT + t))) : (tbase + t);

        float xa0[BT], xa1[BT];
        if (!L0) {
            const int tl = tg - tbase;   // local index in xg chunk, [0, SEGT)
            const float* xg = xgb + ((size_t)tl * BATCH + b0) * G4;
#pragma unroll
            for (int b = 0; b < BT; b++) {
                xa0[b] = xg[b * G4 + g0];
                xa1[b] = xg[b * G4 + g1];
            }
        } else {
            const float4* src = (const float4*)(g_xT + ((size_t)tg * BATCH + b0) * 16);
            for (int i = tid; i < BT * 4; i += 256) {
                int b = i >> 2, c = i & 3;
                *(float4*)&zsm[b * KPAD + c * 4] = src[b * 4 + c];
            }
        }
        __syncthreads();   // x/h ready

        unsigned long long a0[BT], a1[BT];
#pragma unroll
        for (int b = 0; b < BT; b++) {
            a0[b] = L0 ? 0ull : pack2(xa0[b], 0.f);
            a1[b] = L0 ? 0ull : pack2(xa1[b], 0.f);
        }

        ulonglong2 w0n = wp[g0];
        ulonglong2 w1n = wp[g1];
        for (int kk = 0; kk < KQ; kk++) {
            ulonglong2 w0 = w0n, w1 = w1n;
            if (kk + 1 < KQ) {
                w0n = wp[(kk + 1) * G4 + g0];
                w1n = wp[(kk + 1) * G4 + g1];
            }
            const ulonglong2* zq = (const ulonglong2*)(zsm + kk * 4);
#pragma unroll
            for (int b = 0; b < BT; b++) {
                ulonglong2 zb = zq[b * (KPAD / 4)];
                a0[b] = ffma2(zb.x, w0.x, a0[b]);
                a0[b] = ffma2(zb.y, w0.y, a0[b]);
                a1[b] = ffma2(zb.x, w1.x, a1[b]);
                a1[b] = ffma2(zb.y, w1.y, a1[b]);
            }
        }

#pragma unroll
        for (int b = 0; b < BT; b++) {
            gsm[b * G4 + g0] = upsum(a0[b]) + bs0;
            gsm[b * G4 + g1] = upsum(a1[b]) + bs1;
        }
        __syncthreads();

        {
            const int b  = tid >> 4;
            const int j0 = (tid & 15) * 8;
            const float* gb = gsm + b * G4;
            float* cb = csm + b * HID;
            float hv[8];
#pragma unroll
            for (int u = 0; u < 8; u++) {
                int j = j0 + u;
                float gi = sigm(gb[j]);
                float gf = sigm(gb[HID + j]);
                float gg = tanhx(gb[2 * HID + j]);
                float go = sigm(gb[3 * HID + j]);
                float c  = gf * cb[j] + gi * gg;
                cb[j] = c;
                hv[u] = go * tanhx(c);
            }
            float* zh = zsm + b * KPAD + XW + j0;
            *(float4*)zh       = make_float4(hv[0], hv[1], hv[2], hv[3]);
            *(float4*)(zh + 4) = make_float4(hv[4], hv[5], hv[6], hv[7]);
            if (L0) {
                __nv_bfloat162 hb[4], lb[4];
#pragma unroll
                for (int u = 0; u < 4; u++) {
                    __nv_bfloat16 h0 = __float2bfloat16(hv[2 * u]);
                    __nv_bfloat16 h1 = __float2bfloat16(hv[2 * u + 1]);
                    hb[u] = __nv_bfloat162{h0, h1};
                    lb[u] = __nv_bfloat162{
                        __float2bfloat16(hv[2 * u]     - __bfloat162float(h0)),
                        __float2bfloat16(hv[2 * u + 1] - __bfloat162float(h1))};
                }
                size_t rowoff = ((size_t)tg * BATCH + b0 + b) * 256 + dir * HID + j0;
                *(uint4*)(g_ah + rowoff) = *(uint4*)hb;
                *(uint4*)(g_al + rowoff) = *(uint4*)lb;
            }
        }
    }

    if (!L0) {
        __syncthreads();
        for (int i = tid; i < BT * HID; i += 256) {
            int b = i >> 7, j = i & 127;
            g_hstate[(dir * BATCH + b0 + b) * HID + j] = zsm[b * KPAD + XW + j];
            g_cstate[(dir * BATCH + b0 + b) * HID + j] = csm[b * HID + j];
        }
        if (seg == NSEG - 1) {
            for (int i = tid; i < BT * HID; i += 256) {
                int b = i >> 7, j = i & 127;
                g_final[(size_t)(b0 + b) * 256 + dir * HID + j] = zsm[b * KPAD + XW + j];
            }
        }
    }
}

// ---------------------------------------------------------------------------
// Classifier
// ---------------------------------------------------------------------------
__global__ void k_cls(const float* __restrict__ wc, const float* __restrict__ bc,
                      float* __restrict__ out) {
    int gw   = (blockIdx.x * blockDim.x + threadIdx.x) >> 5;
    int lane = threadIdx.x & 31;
    if (gw >= BATCH) return;
    const float* f = g_final + (size_t)gw * 256;
    float v[8];
#pragma unroll
    for (int i = 0; i < 8; i++) v[i] = f[lane + 32 * i];
#pragma unroll
    for (int nc = 0; nc < NCLS; nc++) {
        float s = 0.f;
#pragma unroll
        for (int i = 0; i < 8; i++) s += v[i] * wc[nc * 256 + lane + 32 * i];
#pragma unroll
        for (int off = 16; off; off >>= 1) s += __shfl_down_sync(0xffffffffu, s, off);
        if (lane == 0) out[gw * NCLS + nc] = s + bc[nc];
    }
}

// ---------------------------------------------------------------------------
extern "C" void kernel_launch(void* const* d_in, const int* in_sizes, int n_in,
                              void* d_out, int out_size) {
    (void)in_sizes; (void)n_in; (void)out_size;
    const float* x = (const float*)d_in[0];

    const int smem0 = (BT * KPAD0 + BT * G4 + BT * HID) * 4;           // 50176
    const int smem1 = (BT * KPAD1 + BT * G4 + BT * HID) * 4;           // 49152
    const int smemX = (2 * 128 * BSTR + 2 * 256 * ASTR) * 2;           // 176128
    (void)cudaFuncSetAttribute(k_lstm<true>,  cudaFuncAttributeMaxDynamicSharedMemorySize, 65536);
    (void)cudaFuncSetAttribute(k_lstm<false>, cudaFuncAttributeMaxDynamicSharedMemorySize, 65536);
    (void)cudaFuncSetAttribute(k_xg1,         cudaFuncAttributeMaxDynamicSharedMemorySize, smemX);

    WPtrs W;
    for (int i = 0; i < 16; i++) W.p[i] = (const float*)d_in[1 + i];

    k_transpose<<<(TLEN * BATCH * 16 + 255) / 256, 256>>>(x);
    k_pack_whh<<<dim3((KPAD0 * G4 + 255) / 256, 4), 256>>>(W);
    k_pack_wb1<<<(2 * G4 * 256 + 255) / 256, 256>>>((const float*)d_in[9], (const float*)d_in[13]);

    k_lstm<true ><<<dim3(BATCH / BT, 2), 256, smem0>>>(0);
    for (int seg = 0; seg < NSEG; seg++) {
        k_xg1<<<dim3((SEGT * BATCH) / 256, 8), 256, smemX>>>(seg);
        k_lstm<false><<<dim3(BATCH / BT, 2), 256, smem1>>>(seg);
    }

    k_cls<<<BATCH / 8, 256>>>((const float*)d_in[17], (const float*)d_in[18], (float*)d_out);
}